// round 5
// baseline (speedup 1.0000x reference)
#include <cuda_runtime.h>

// x: (B=64, W=512, H=48, M=64) float32, row-major.
// out[b, iw*(6*64) + ih*64 + m] = max_{w in [32iw,32iw+32), h in [8ih,8ih+8)} x[b,w,h,m]
//
// Block: one (b, iw) tile. 384 threads = 4 w-splits x 96 (ih, m4) float4 outputs.
// Each thread: 64 streaming float4 loads (8 w-rows x 8 h) through a rolling
// 16-register window: consume v[j], immediately reissue its replacement.
// MLP stays ~16 continuously (no batch-drain sawtooth), then 4-way shared max.

#define NB 64
#define NW 512
#define NH 48
#define NM 64
#define PW 16
#define PH 6
#define ROW_F4 768   // float4 per (b,w) row = 48*64/4
#define H_F4 16      // float4 per h step

__device__ __forceinline__ float4 ld_cs(const float4* p) {
    float4 v;
    asm volatile("ld.global.cs.v4.f32 {%0,%1,%2,%3}, [%4];"
                 : "=f"(v.x), "=f"(v.y), "=f"(v.z), "=f"(v.w) : "l"(p));
    return v;
}

__device__ __forceinline__ float4 f4max(float4 a, float4 b) {
    a.x = fmaxf(a.x, b.x);
    a.y = fmaxf(a.y, b.y);
    a.z = fmaxf(a.z, b.z);
    a.w = fmaxf(a.w, b.w);
    return a;
}

__global__ __launch_bounds__(384, 2)
void dap_pool_kernel(const float4* __restrict__ x, float4* __restrict__ out) {
    const int blk = blockIdx.x;       // b*16 + iw
    const int b  = blk >> 4;
    const int iw = blk & 15;
    const int tid = threadIdx.x;      // 0..383
    const int ws  = tid / 96;         // w-split 0..3 (8 w-rows each)
    const int om  = tid - ws * 96;    // ih*16 + m4
    const int ih  = om >> 4;
    const int m4  = om & 15;

    // base float4 index of x[b, iw*32 + ws*8, ih*8, m4*4]
    const size_t base = ((size_t)(b * NW + iw * 32 + ws * 8) * NH + ih * 8) * H_F4 + m4;
    const float4* p = x + base;

    // Rolling window: v[j] holds load j of the current 2-row group (rows 2k, 2k+1).
    // Window slot j -> row parity (j>>3), h index (j&7).
    float4 v[16];

    // Prologue: rows 0,1
    #pragma unroll
    for (int j = 0; j < 16; j++) {
        v[j] = ld_cs(p + (size_t)(j >> 3) * ROW_F4 + (j & 7) * H_F4);
    }

    float4 acc = make_float4(-__FLT_MAX__, -__FLT_MAX__, -__FLT_MAX__, -__FLT_MAX__);

    // Steady state: consume group k-1, refill with group k (rows 2k, 2k+1)
    #pragma unroll 1
    for (int k = 1; k < 4; k++) {
        const float4* q = p + (size_t)(2 * k) * ROW_F4;
        #pragma unroll
        for (int j = 0; j < 16; j++) {
            float4 nv = ld_cs(q + (size_t)(j >> 3) * ROW_F4 + (j & 7) * H_F4);
            acc = f4max(acc, v[j]);
            v[j] = nv;
        }
    }

    // Epilogue: consume last group (tree to shorten the dependent chain)
    #pragma unroll
    for (int j = 0; j < 8; j++) v[j] = f4max(v[j], v[j + 8]);
    #pragma unroll
    for (int j = 0; j < 4; j++) v[j] = f4max(v[j], v[j + 4]);
    v[0] = f4max(v[0], v[1]);
    v[2] = f4max(v[2], v[3]);
    acc = f4max(acc, f4max(v[0], v[2]));

    __shared__ float4 smem[384];
    smem[tid] = acc;
    __syncthreads();

    if (tid < 96) {
        float4 a = smem[tid];
        a = f4max(a, smem[tid + 96]);
        a = f4max(a, smem[tid + 192]);
        a = f4max(a, smem[tid + 288]);
        out[(size_t)b * (PW * PH * (NM / 4)) + iw * (PH * (NM / 4)) + tid] = a;
    }
}

extern "C" void kernel_launch(void* const* d_in, const int* in_sizes, int n_in,
                              void* d_out, int out_size) {
    (void)in_sizes; (void)n_in; (void)out_size;
    const float4* x = (const float4*)d_in[0];
    float4* out = (float4*)d_out;
    dap_pool_kernel<<<NB * PW, 384>>>(x, out);
}

// round 6
// speedup vs baseline: 1.5137x; 1.5137x over previous
#include <cuda_runtime.h>
#include <cstdint>

// x: (B=64, W=512, H=48, M=64) float32, row-major.
// out[b, iw*(6*64) + ih*64 + m] = max over w in [32iw,32iw+32), h in [8ih,8ih+8).
//
// Each block owns one (b, iw) tile = 32 contiguous w-rows = 384 KB contiguous.
// TMA (cp.async.bulk) streams it through a 2-stage x 48 KB smem pipeline
// (4 w-rows per chunk, 8 chunks). 384 threads = 4 rows x 96 (ih,m4) consumers
// reduce each chunk from smem (conflict-free LDS.128), then a 4-way shared
// combine produces the 96 float4 outputs.

#define NB 64
#define NW 512
#define NH 48
#define NM 64
#define PW 16
#define PH 6
#define ROW_F4 768                 // float4 per w-row (48*64/4)
#define ROWS_PER_CHUNK 4
#define CHUNK_BYTES (ROWS_PER_CHUNK * ROW_F4 * 16)   // 49152
#define CHUNK_F4 (ROWS_PER_CHUNK * ROW_F4)           // 3072
#define NCHUNKS 8
#define NSTAGES 2
#define SMEM_DATA_OFF 128
#define SMEM_BYTES (SMEM_DATA_OFF + NSTAGES * CHUNK_BYTES)  // 98432

__device__ __forceinline__ uint32_t smem_u32(const void* p) {
    uint32_t a;
    asm("{ .reg .u64 t; cvta.to.shared.u64 t, %1; cvt.u32.u64 %0, t; }" : "=r"(a) : "l"(p));
    return a;
}

__device__ __forceinline__ void mbar_init(uint32_t mbar, uint32_t count) {
    asm volatile("mbarrier.init.shared.b64 [%0], %1;" :: "r"(mbar), "r"(count) : "memory");
}

__device__ __forceinline__ void mbar_expect_tx(uint32_t mbar, uint32_t bytes) {
    asm volatile("mbarrier.arrive.expect_tx.shared.b64 _, [%0], %1;" :: "r"(mbar), "r"(bytes) : "memory");
}

__device__ __forceinline__ void mbar_arrive(uint32_t mbar) {
    asm volatile("mbarrier.arrive.shared.b64 _, [%0];" :: "r"(mbar) : "memory");
}

__device__ __forceinline__ void mbar_wait(uint32_t mbar, uint32_t parity) {
    uint32_t done;
    asm volatile(
        "{\n\t"
        ".reg .pred p;\n\t"
        "mbarrier.try_wait.parity.acquire.cta.shared::cta.b64 p, [%1], %2;\n\t"
        "selp.b32 %0, 1, 0, p;\n\t"
        "}"
        : "=r"(done) : "r"(mbar), "r"(parity) : "memory");
    if (!done) {
        asm volatile(
            "{\n\t"
            ".reg .pred P1;\n\t"
            "WL_%=:\n\t"
            "mbarrier.try_wait.parity.acquire.cta.shared::cta.b64 P1, [%0], %1, 0x989680;\n\t"
            "@P1 bra.uni WD_%=;\n\t"
            "bra.uni WL_%=;\n\t"
            "WD_%=:\n\t"
            "}"
            :: "r"(mbar), "r"(parity) : "memory");
    }
}

__device__ __forceinline__ void bulk_ldg(uint32_t dst_smem, const void* src, uint32_t bytes, uint32_t mbar) {
    asm volatile(
        "cp.async.bulk.shared::cluster.global.mbarrier::complete_tx::bytes [%0], [%1], %2, [%3];"
        :: "r"(dst_smem), "l"(src), "r"(bytes), "r"(mbar) : "memory");
}

__device__ __forceinline__ float4 f4max(float4 a, float4 b) {
    a.x = fmaxf(a.x, b.x);
    a.y = fmaxf(a.y, b.y);
    a.z = fmaxf(a.z, b.z);
    a.w = fmaxf(a.w, b.w);
    return a;
}

__global__ __launch_bounds__(384, 2)
void dap_pool_tma_kernel(const float4* __restrict__ x, float4* __restrict__ out) {
    extern __shared__ __align__(128) unsigned char smem_raw[];
    const uint32_t smem_base = smem_u32(smem_raw);
    // barriers: full[s] at s*16, empty[s] at s*16+8
    const uint32_t full0  = smem_base + 0;
    const uint32_t full1  = smem_base + 16;
    const uint32_t empty0 = smem_base + 8;
    const uint32_t empty1 = smem_base + 24;

    const int blk = blockIdx.x;       // b*16 + iw
    const int b  = blk >> 4;
    const int iw = blk & 15;
    const int tid = threadIdx.x;      // 0..383
    const int row = tid / 96;         // w-row within chunk (0..3)
    const int pos = tid - row * 96;   // ih*16 + m4
    const int ih  = pos >> 4;
    const int m4  = pos & 15;

    if (tid == 0) {
        mbar_init(full0, 1);
        mbar_init(full1, 1);
        mbar_init(empty0, 384);
        mbar_init(empty1, 384);
        asm volatile("fence.proxy.async.shared::cta;" ::: "memory");
    }
    __syncthreads();

    // tile base: x[b, iw*32, 0, 0], contiguous 32 rows * 12 KB
    const float4* src0 = x + (size_t)(b * NW + iw * 32) * ROW_F4;
    const float4* sdata = (const float4*)(smem_raw + SMEM_DATA_OFF);
    const int rdbase = row * ROW_F4 + ih * 128 + m4;   // float4 index within chunk

    float4 acc = make_float4(-__FLT_MAX__, -__FLT_MAX__, -__FLT_MAX__, -__FLT_MAX__);

    int full_ph[2]  = {0, 0};
    int empty_ph[2] = {0, 0};

    #pragma unroll 1
    for (int k = 0; k < NCHUNKS; k++) {
        const int s = k & 1;
        const uint32_t fullb  = s ? full1 : full0;
        const uint32_t emptyb = s ? empty1 : empty0;
        const uint32_t dst = smem_base + SMEM_DATA_OFF + s * CHUNK_BYTES;

        if (tid == 0) {
            if (k >= NSTAGES) {           // stage reuse: wait for consumers of chunk k-2
                mbar_wait(emptyb, empty_ph[s]);
                empty_ph[s] ^= 1;
            }
            mbar_expect_tx(fullb, CHUNK_BYTES);
            bulk_ldg(dst, src0 + (size_t)k * CHUNK_F4, CHUNK_BYTES, fullb);
        }

        mbar_wait(fullb, full_ph[s]);
        full_ph[s] ^= 1;

        const float4* c = sdata + s * CHUNK_F4 + rdbase;
        float4 v0 = c[0 * 16];
        float4 v1 = c[1 * 16];
        float4 v2 = c[2 * 16];
        float4 v3 = c[3 * 16];
        float4 v4 = c[4 * 16];
        float4 v5 = c[5 * 16];
        float4 v6 = c[6 * 16];
        float4 v7 = c[7 * 16];
        v0 = f4max(v0, v1);
        v2 = f4max(v2, v3);
        v4 = f4max(v4, v5);
        v6 = f4max(v6, v7);
        v0 = f4max(v0, v2);
        v4 = f4max(v4, v6);
        acc = f4max(acc, f4max(v0, v4));

        mbar_arrive(emptyb);
    }

    // cross-row combine: reuse data smem (all chunks fully consumed)
    __syncthreads();
    float4* red = (float4*)(smem_raw + SMEM_DATA_OFF);
    red[tid] = acc;
    __syncthreads();

    if (tid < 96) {
        float4 a = red[tid];
        a = f4max(a, red[tid + 96]);
        a = f4max(a, red[tid + 192]);
        a = f4max(a, red[tid + 288]);
        out[(size_t)b * (PW * PH * (NM / 4)) + iw * (PH * (NM / 4)) + tid] = a;
    }
}

extern "C" void kernel_launch(void* const* d_in, const int* in_sizes, int n_in,
                              void* d_out, int out_size) {
    (void)in_sizes; (void)n_in; (void)out_size;
    const float4* x = (const float4*)d_in[0];
    float4* out = (float4*)d_out;
    cudaFuncSetAttribute(dap_pool_tma_kernel,
                         cudaFuncAttributeMaxDynamicSharedMemorySize, SMEM_BYTES);
    dap_pool_tma_kernel<<<NB * PW, 384, SMEM_BYTES>>>(x, out);
}

// round 7
// speedup vs baseline: 1.5584x; 1.0296x over previous
#include <cuda_runtime.h>

// x: (B=64, W=512, H=48, M=64) float32, row-major.
// out[b, iw*(6*64) + ih*64 + m] = max over w in [32iw,32iw+32), h in [8ih,8ih+8).
//
// Block: one (b, iw) tile, 768 threads = 8 w-splits x 96 (ih,m4) float4 outputs.
// Each thread: 4 w-rows, batch-8 streaming float4 loads per row (MLP_p1=8),
// 2 CTAs/SM (oe*MLP_p1 = 16 = L1tex-queue contention threshold), then 8-way
// shared-memory combine.

#define NB 64
#define NW 512
#define NH 48
#define NM 64
#define PW 16
#define PH 6
#define ROW_F4 768   // float4 per (b,w) row = 48*64/4
#define H_F4 16      // float4 per h step

__device__ __forceinline__ float4 ld_cs(const float4* p) {
    float4 v;
    asm volatile("ld.global.cs.v4.f32 {%0,%1,%2,%3}, [%4];"
                 : "=f"(v.x), "=f"(v.y), "=f"(v.z), "=f"(v.w) : "l"(p));
    return v;
}

__device__ __forceinline__ float4 f4max(float4 a, float4 b) {
    a.x = fmaxf(a.x, b.x);
    a.y = fmaxf(a.y, b.y);
    a.z = fmaxf(a.z, b.z);
    a.w = fmaxf(a.w, b.w);
    return a;
}

__global__ __launch_bounds__(768, 2)
void dap_pool_kernel(const float4* __restrict__ x, float4* __restrict__ out) {
    const int blk = blockIdx.x;       // b*16 + iw
    const int b  = blk >> 4;
    const int iw = blk & 15;
    const int tid = threadIdx.x;      // 0..767
    const int ws  = tid / 96;         // w-split 0..7 (4 w-rows each)
    const int om  = tid - ws * 96;    // ih*16 + m4
    const int ih  = om >> 4;
    const int m4  = om & 15;

    // base float4 index of x[b, iw*32 + ws*4, ih*8, m4*4]
    const size_t base = ((size_t)(b * NW + iw * 32 + ws * 4) * NH + ih * 8) * H_F4 + m4;
    const float4* p = x + base;

    float4 acc = make_float4(-__FLT_MAX__, -__FLT_MAX__, -__FLT_MAX__, -__FLT_MAX__);

    #pragma unroll 1
    for (int wl = 0; wl < 4; wl++) {
        const float4* q = p + (size_t)wl * ROW_F4;
        float4 v0 = ld_cs(q + 0 * H_F4);
        float4 v1 = ld_cs(q + 1 * H_F4);
        float4 v2 = ld_cs(q + 2 * H_F4);
        float4 v3 = ld_cs(q + 3 * H_F4);
        float4 v4 = ld_cs(q + 4 * H_F4);
        float4 v5 = ld_cs(q + 5 * H_F4);
        float4 v6 = ld_cs(q + 6 * H_F4);
        float4 v7 = ld_cs(q + 7 * H_F4);
        v0 = f4max(v0, v1);
        v2 = f4max(v2, v3);
        v4 = f4max(v4, v5);
        v6 = f4max(v6, v7);
        v0 = f4max(v0, v2);
        v4 = f4max(v4, v6);
        acc = f4max(acc, f4max(v0, v4));
    }

    __shared__ float4 smem[768];
    smem[tid] = acc;
    __syncthreads();

    if (tid < 96) {
        float4 a = smem[tid];
        #pragma unroll
        for (int s = 1; s < 8; s++) a = f4max(a, smem[tid + s * 96]);
        out[(size_t)b * (PW * PH * (NM / 4)) + iw * (PH * (NM / 4)) + tid] = a;
    }
}

extern "C" void kernel_launch(void* const* d_in, const int* in_sizes, int n_in,
                              void* d_out, int out_size) {
    (void)in_sizes; (void)n_in; (void)out_size;
    const float4* x = (const float4*)d_in[0];
    float4* out = (float4*)d_out;
    dap_pool_kernel<<<NB * PW, 768>>>(x, out);
}